// round 15
// baseline (speedup 1.0000x reference)
#include <cuda_runtime.h>
#include <cuda_bf16.h>
#include <cstdint>

// out[b,m,c] = sum_{k<3} vals[m,k] * x[b, cols[m,k], c]
//   x: [8, 50000, 128] f32   cols: [25000, 3] i32   vals: [25000, 3] f32
//   out: [8, 25000, 128] f32
//
// Design-space closure round: (1m x 4b) per warp at MLP=12 — the last
// untested work shape at this register budget. vs the converged (2m x 2b):
//  - half the uniform index/weight loads per warp
//  - concurrent hot L2 footprint = 4 batch slices (~80MB touched) instead
//    of 2 (~40MB); tests whether within-replay duplicate-row reuse capture
//    survives a 2x larger hotset (still < 126MB L2).
// Keeps every proven element: 12 independent coalesced LDG.128 per lane,
// st.global.wt output (write-through; no dirty-line L2 cycling), monotone
// batch-group order.

#define B_DIM 8
#define N_DIM 50000
#define M_DIM 25000
#define C_VEC 32              // 128 floats / 4 per float4
#define BG    (B_DIM / 4)     // 2 batch groups of 4

__device__ __forceinline__ void stwt(float4* p, float4 v) {
    asm volatile("st.global.wt.v4.f32 [%0], {%1,%2,%3,%4};"
                 :: "l"(p), "f"(v.x), "f"(v.y), "f"(v.z), "f"(v.w));
}

__global__ __launch_bounds__(256, 3)
void mesh_sampling_kernel(const float4* __restrict__ x,
                          const int*    __restrict__ cols,
                          const float*  __restrict__ vals,
                          float4*       __restrict__ out)
{
    const int gwarp = (blockIdx.x * blockDim.x + threadIdx.x) >> 5;
    const int lane  = threadIdx.x & 31;
    if (gwarp >= BG * M_DIM) return;

    const int bg = gwarp / M_DIM;        // batch group 0..1
    const int m  = gwarp - bg * M_DIM;
    const int b0 = bg * 4;               // batches b0..b0+3

    // warp-uniform indices / weights (broadcast, L2-resident)
    const int  c0 = __ldg(cols + m * 3 + 0);
    const int  c1 = __ldg(cols + m * 3 + 1);
    const int  c2 = __ldg(cols + m * 3 + 2);
    const float v0 = __ldg(vals + m * 3 + 0);
    const float v1 = __ldg(vals + m * 3 + 1);
    const float v2 = __ldg(vals + m * 3 + 2);

    const float4* xb0 = x + (size_t)(b0 + 0) * N_DIM * C_VEC + lane;
    const float4* xb1 = x + (size_t)(b0 + 1) * N_DIM * C_VEC + lane;
    const float4* xb2 = x + (size_t)(b0 + 2) * N_DIM * C_VEC + lane;
    const float4* xb3 = x + (size_t)(b0 + 3) * N_DIM * C_VEC + lane;

    const size_t o0 = (size_t)c0 * C_VEC;
    const size_t o1 = (size_t)c1 * C_VEC;
    const size_t o2 = (size_t)c2 * C_VEC;

    // 12 independent 16B loads in flight, all 512B-row coalesced
    const float4 a00 = __ldg(xb0 + o0);
    const float4 a01 = __ldg(xb0 + o1);
    const float4 a02 = __ldg(xb0 + o2);
    const float4 a10 = __ldg(xb1 + o0);
    const float4 a11 = __ldg(xb1 + o1);
    const float4 a12 = __ldg(xb1 + o2);
    const float4 a20 = __ldg(xb2 + o0);
    const float4 a21 = __ldg(xb2 + o1);
    const float4 a22 = __ldg(xb2 + o2);
    const float4 a30 = __ldg(xb3 + o0);
    const float4 a31 = __ldg(xb3 + o1);
    const float4 a32 = __ldg(xb3 + o2);

    float4 r;
    // batch b0+0
    r.x = v0 * a00.x + v1 * a01.x + v2 * a02.x;
    r.y = v0 * a00.y + v1 * a01.y + v2 * a02.y;
    r.z = v0 * a00.z + v1 * a01.z + v2 * a02.z;
    r.w = v0 * a00.w + v1 * a01.w + v2 * a02.w;
    stwt(out + ((size_t)(b0 + 0) * M_DIM + m) * C_VEC + lane, r);
    // batch b0+1
    r.x = v0 * a10.x + v1 * a11.x + v2 * a12.x;
    r.y = v0 * a10.y + v1 * a11.y + v2 * a12.y;
    r.z = v0 * a10.z + v1 * a11.z + v2 * a12.z;
    r.w = v0 * a10.w + v1 * a11.w + v2 * a12.w;
    stwt(out + ((size_t)(b0 + 1) * M_DIM + m) * C_VEC + lane, r);
    // batch b0+2
    r.x = v0 * a20.x + v1 * a21.x + v2 * a22.x;
    r.y = v0 * a20.y + v1 * a21.y + v2 * a22.y;
    r.z = v0 * a20.z + v1 * a21.z + v2 * a22.z;
    r.w = v0 * a20.w + v1 * a21.w + v2 * a22.w;
    stwt(out + ((size_t)(b0 + 2) * M_DIM + m) * C_VEC + lane, r);
    // batch b0+3
    r.x = v0 * a30.x + v1 * a31.x + v2 * a32.x;
    r.y = v0 * a30.y + v1 * a31.y + v2 * a32.y;
    r.z = v0 * a30.z + v1 * a31.z + v2 * a32.z;
    r.w = v0 * a30.w + v1 * a31.w + v2 * a32.w;
    stwt(out + ((size_t)(b0 + 3) * M_DIM + m) * C_VEC + lane, r);
}

extern "C" void kernel_launch(void* const* d_in, const int* in_sizes, int n_in,
                              void* d_out, int out_size)
{
    const float4* x    = (const float4*)d_in[0];
    const int*    cols = (const int*)d_in[1];
    const float*  vals = (const float*)d_in[2];
    float4*       out  = (float4*)d_out;

    const int total_warps   = BG * M_DIM;             // 50000
    const int threads       = 256;
    const int warps_per_blk = threads / 32;
    const int blocks        = (total_warps + warps_per_blk - 1) / warps_per_blk;

    mesh_sampling_kernel<<<blocks, threads>>>(x, cols, vals, out);
}

// round 16
// speedup vs baseline: 1.0267x; 1.0267x over previous
#include <cuda_runtime.h>
#include <cuda_bf16.h>
#include <cstdint>

// out[b,m,c] = sum_{k<3} vals[m,k] * x[b, cols[m,k], c]
//   x: [8, 50000, 128] f32   cols: [25000, 3] i32   vals: [25000, 3] f32
//   out: [8, 25000, 128] f32
//
// Design-space closure round: (1m x 4b) per warp at MLP=12 — the last
// untested work shape at this register budget. vs the converged (2m x 2b):
//  - half the uniform index/weight loads per warp
//  - concurrent hot L2 footprint = 4 batch slices (~80MB touched) instead
//    of 2 (~40MB); tests whether within-replay duplicate-row reuse capture
//    survives a 2x larger hotset (still < 126MB L2).
// Keeps every proven element: 12 independent coalesced LDG.128 per lane,
// st.global.wt output (write-through; no dirty-line L2 cycling), monotone
// batch-group order.

#define B_DIM 8
#define N_DIM 50000
#define M_DIM 25000
#define C_VEC 32              // 128 floats / 4 per float4
#define BG    (B_DIM / 4)     // 2 batch groups of 4

__device__ __forceinline__ void stwt(float4* p, float4 v) {
    asm volatile("st.global.wt.v4.f32 [%0], {%1,%2,%3,%4};"
                 :: "l"(p), "f"(v.x), "f"(v.y), "f"(v.z), "f"(v.w));
}

__global__ __launch_bounds__(256, 3)
void mesh_sampling_kernel(const float4* __restrict__ x,
                          const int*    __restrict__ cols,
                          const float*  __restrict__ vals,
                          float4*       __restrict__ out)
{
    const int gwarp = (blockIdx.x * blockDim.x + threadIdx.x) >> 5;
    const int lane  = threadIdx.x & 31;
    if (gwarp >= BG * M_DIM) return;

    const int bg = gwarp / M_DIM;        // batch group 0..1
    const int m  = gwarp - bg * M_DIM;
    const int b0 = bg * 4;               // batches b0..b0+3

    // warp-uniform indices / weights (broadcast, L2-resident)
    const int  c0 = __ldg(cols + m * 3 + 0);
    const int  c1 = __ldg(cols + m * 3 + 1);
    const int  c2 = __ldg(cols + m * 3 + 2);
    const float v0 = __ldg(vals + m * 3 + 0);
    const float v1 = __ldg(vals + m * 3 + 1);
    const float v2 = __ldg(vals + m * 3 + 2);

    const float4* xb0 = x + (size_t)(b0 + 0) * N_DIM * C_VEC + lane;
    const float4* xb1 = x + (size_t)(b0 + 1) * N_DIM * C_VEC + lane;
    const float4* xb2 = x + (size_t)(b0 + 2) * N_DIM * C_VEC + lane;
    const float4* xb3 = x + (size_t)(b0 + 3) * N_DIM * C_VEC + lane;

    const size_t o0 = (size_t)c0 * C_VEC;
    const size_t o1 = (size_t)c1 * C_VEC;
    const size_t o2 = (size_t)c2 * C_VEC;

    // 12 independent 16B loads in flight, all 512B-row coalesced
    const float4 a00 = __ldg(xb0 + o0);
    const float4 a01 = __ldg(xb0 + o1);
    const float4 a02 = __ldg(xb0 + o2);
    const float4 a10 = __ldg(xb1 + o0);
    const float4 a11 = __ldg(xb1 + o1);
    const float4 a12 = __ldg(xb1 + o2);
    const float4 a20 = __ldg(xb2 + o0);
    const float4 a21 = __ldg(xb2 + o1);
    const float4 a22 = __ldg(xb2 + o2);
    const float4 a30 = __ldg(xb3 + o0);
    const float4 a31 = __ldg(xb3 + o1);
    const float4 a32 = __ldg(xb3 + o2);

    float4 r;
    // batch b0+0
    r.x = v0 * a00.x + v1 * a01.x + v2 * a02.x;
    r.y = v0 * a00.y + v1 * a01.y + v2 * a02.y;
    r.z = v0 * a00.z + v1 * a01.z + v2 * a02.z;
    r.w = v0 * a00.w + v1 * a01.w + v2 * a02.w;
    stwt(out + ((size_t)(b0 + 0) * M_DIM + m) * C_VEC + lane, r);
    // batch b0+1
    r.x = v0 * a10.x + v1 * a11.x + v2 * a12.x;
    r.y = v0 * a10.y + v1 * a11.y + v2 * a12.y;
    r.z = v0 * a10.z + v1 * a11.z + v2 * a12.z;
    r.w = v0 * a10.w + v1 * a11.w + v2 * a12.w;
    stwt(out + ((size_t)(b0 + 1) * M_DIM + m) * C_VEC + lane, r);
    // batch b0+2
    r.x = v0 * a20.x + v1 * a21.x + v2 * a22.x;
    r.y = v0 * a20.y + v1 * a21.y + v2 * a22.y;
    r.z = v0 * a20.z + v1 * a21.z + v2 * a22.z;
    r.w = v0 * a20.w + v1 * a21.w + v2 * a22.w;
    stwt(out + ((size_t)(b0 + 2) * M_DIM + m) * C_VEC + lane, r);
    // batch b0+3
    r.x = v0 * a30.x + v1 * a31.x + v2 * a32.x;
    r.y = v0 * a30.y + v1 * a31.y + v2 * a32.y;
    r.z = v0 * a30.z + v1 * a31.z + v2 * a32.z;
    r.w = v0 * a30.w + v1 * a31.w + v2 * a32.w;
    stwt(out + ((size_t)(b0 + 3) * M_DIM + m) * C_VEC + lane, r);
}

extern "C" void kernel_launch(void* const* d_in, const int* in_sizes, int n_in,
                              void* d_out, int out_size)
{
    const float4* x    = (const float4*)d_in[0];
    const int*    cols = (const int*)d_in[1];
    const float*  vals = (const float*)d_in[2];
    float4*       out  = (float4*)d_out;

    const int total_warps   = BG * M_DIM;             // 50000
    const int threads       = 256;
    const int warps_per_blk = threads / 32;
    const int blocks        = (total_warps + warps_per_blk - 1) / warps_per_blk;

    mesh_sampling_kernel<<<blocks, threads>>>(x, cols, vals, out);
}

// round 17
// speedup vs baseline: 1.0329x; 1.0060x over previous
#include <cuda_runtime.h>
#include <cuda_bf16.h>
#include <cstdint>

// out[b,m,c] = sum_{k<3} vals[m,k] * x[b, cols[m,k], c]
//   x: [8, 50000, 128] f32   cols: [25000, 3] i32   vals: [25000, 3] f32
//   out: [8, 25000, 128] f32
//
// Design-space closure round: (1m x 4b) per warp at MLP=12 — the last
// untested work shape at this register budget. vs the converged (2m x 2b):
//  - half the uniform index/weight loads per warp
//  - concurrent hot L2 footprint = 4 batch slices (~80MB touched) instead
//    of 2 (~40MB); tests whether within-replay duplicate-row reuse capture
//    survives a 2x larger hotset (still < 126MB L2).
// Keeps every proven element: 12 independent coalesced LDG.128 per lane,
// st.global.wt output (write-through; no dirty-line L2 cycling), monotone
// batch-group order.

#define B_DIM 8
#define N_DIM 50000
#define M_DIM 25000
#define C_VEC 32              // 128 floats / 4 per float4
#define BG    (B_DIM / 4)     // 2 batch groups of 4

__device__ __forceinline__ void stwt(float4* p, float4 v) {
    asm volatile("st.global.wt.v4.f32 [%0], {%1,%2,%3,%4};"
                 :: "l"(p), "f"(v.x), "f"(v.y), "f"(v.z), "f"(v.w));
}

__global__ __launch_bounds__(256, 3)
void mesh_sampling_kernel(const float4* __restrict__ x,
                          const int*    __restrict__ cols,
                          const float*  __restrict__ vals,
                          float4*       __restrict__ out)
{
    const int gwarp = (blockIdx.x * blockDim.x + threadIdx.x) >> 5;
    const int lane  = threadIdx.x & 31;
    if (gwarp >= BG * M_DIM) return;

    const int bg = gwarp / M_DIM;        // batch group 0..1
    const int m  = gwarp - bg * M_DIM;
    const int b0 = bg * 4;               // batches b0..b0+3

    // warp-uniform indices / weights (broadcast, L2-resident)
    const int  c0 = __ldg(cols + m * 3 + 0);
    const int  c1 = __ldg(cols + m * 3 + 1);
    const int  c2 = __ldg(cols + m * 3 + 2);
    const float v0 = __ldg(vals + m * 3 + 0);
    const float v1 = __ldg(vals + m * 3 + 1);
    const float v2 = __ldg(vals + m * 3 + 2);

    const float4* xb0 = x + (size_t)(b0 + 0) * N_DIM * C_VEC + lane;
    const float4* xb1 = x + (size_t)(b0 + 1) * N_DIM * C_VEC + lane;
    const float4* xb2 = x + (size_t)(b0 + 2) * N_DIM * C_VEC + lane;
    const float4* xb3 = x + (size_t)(b0 + 3) * N_DIM * C_VEC + lane;

    const size_t o0 = (size_t)c0 * C_VEC;
    const size_t o1 = (size_t)c1 * C_VEC;
    const size_t o2 = (size_t)c2 * C_VEC;

    // 12 independent 16B loads in flight, all 512B-row coalesced
    const float4 a00 = __ldg(xb0 + o0);
    const float4 a01 = __ldg(xb0 + o1);
    const float4 a02 = __ldg(xb0 + o2);
    const float4 a10 = __ldg(xb1 + o0);
    const float4 a11 = __ldg(xb1 + o1);
    const float4 a12 = __ldg(xb1 + o2);
    const float4 a20 = __ldg(xb2 + o0);
    const float4 a21 = __ldg(xb2 + o1);
    const float4 a22 = __ldg(xb2 + o2);
    const float4 a30 = __ldg(xb3 + o0);
    const float4 a31 = __ldg(xb3 + o1);
    const float4 a32 = __ldg(xb3 + o2);

    float4 r;
    // batch b0+0
    r.x = v0 * a00.x + v1 * a01.x + v2 * a02.x;
    r.y = v0 * a00.y + v1 * a01.y + v2 * a02.y;
    r.z = v0 * a00.z + v1 * a01.z + v2 * a02.z;
    r.w = v0 * a00.w + v1 * a01.w + v2 * a02.w;
    stwt(out + ((size_t)(b0 + 0) * M_DIM + m) * C_VEC + lane, r);
    // batch b0+1
    r.x = v0 * a10.x + v1 * a11.x + v2 * a12.x;
    r.y = v0 * a10.y + v1 * a11.y + v2 * a12.y;
    r.z = v0 * a10.z + v1 * a11.z + v2 * a12.z;
    r.w = v0 * a10.w + v1 * a11.w + v2 * a12.w;
    stwt(out + ((size_t)(b0 + 1) * M_DIM + m) * C_VEC + lane, r);
    // batch b0+2
    r.x = v0 * a20.x + v1 * a21.x + v2 * a22.x;
    r.y = v0 * a20.y + v1 * a21.y + v2 * a22.y;
    r.z = v0 * a20.z + v1 * a21.z + v2 * a22.z;
    r.w = v0 * a20.w + v1 * a21.w + v2 * a22.w;
    stwt(out + ((size_t)(b0 + 2) * M_DIM + m) * C_VEC + lane, r);
    // batch b0+3
    r.x = v0 * a30.x + v1 * a31.x + v2 * a32.x;
    r.y = v0 * a30.y + v1 * a31.y + v2 * a32.y;
    r.z = v0 * a30.z + v1 * a31.z + v2 * a32.z;
    r.w = v0 * a30.w + v1 * a31.w + v2 * a32.w;
    stwt(out + ((size_t)(b0 + 3) * M_DIM + m) * C_VEC + lane, r);
}

extern "C" void kernel_launch(void* const* d_in, const int* in_sizes, int n_in,
                              void* d_out, int out_size)
{
    const float4* x    = (const float4*)d_in[0];
    const int*    cols = (const int*)d_in[1];
    const float*  vals = (const float*)d_in[2];
    float4*       out  = (float4*)d_out;

    const int total_warps   = BG * M_DIM;             // 50000
    const int threads       = 256;
    const int warps_per_blk = threads / 32;
    const int blocks        = (total_warps + warps_per_blk - 1) / warps_per_blk;

    mesh_sampling_kernel<<<blocks, threads>>>(x, cols, vals, out);
}